// round 2
// baseline (speedup 1.0000x reference)
#include <cuda_runtime.h>
#include <math.h>

#define NN    50000
#define EE    800000
#define TT    32
#define CH    64          // CHUNK = CIN/T
#define HH    96
#define CIN   2048
#define EPS_BN 1e-5f
#define VTH    0.005f

// ---------------- persistent device scratch (no allocation allowed) -------
__device__ int   g_deg[NN];
__device__ int   g_cnt[NN];
__device__ int   g_off[NN + 1];
__device__ int   g_csrc[EE];
__device__ float g_cw[EE];
__device__ float g_dinv[NN];
__device__ float g_snorm[NN];
__device__ float g_rsum[NN];
__device__ float g_aggx[NN * CH];   // A_full @ x_chunk
__device__ float g_h2[NN * HH];     // bns(elu(z1))
__device__ float g_agg2[NN * HH];   // A_full @ h2
__device__ float g_v[NN * HH];      // PLIF membrane state
__device__ float g_ss[HH];          // shared-BN scale
__device__ float g_cs[HH];          // shared-BN shift
__device__ float g_lwsum[HH];       // sum(lin_w, axis=0)

// ---------------- preprocessing kernels ----------------------------------
__global__ void k_init() {
    int i = blockIdx.x * blockDim.x + threadIdx.x;
    if (i < NN) { g_deg[i] = 0; g_cnt[i] = 0; }
}

__global__ void k_zero_v() {
    int i = blockIdx.x * blockDim.x + threadIdx.x;
    if (i < NN * HH) g_v[i] = 0.f;
}

__global__ void k_deg(const int* __restrict__ ei) {
    int e = blockIdx.x * blockDim.x + threadIdx.x;
    if (e < EE) atomicAdd(&g_deg[ei[EE + e]], 1);
}

__global__ void k_dinv() {
    int i = blockIdx.x * blockDim.x + threadIdx.x;
    if (i < NN) {
        float d = (float)(g_deg[i] + 1);
        g_dinv[i]  = rsqrtf(d);
        g_snorm[i] = 1.0f / d;
    }
}

// single-block exclusive scan of g_deg -> g_off
__global__ void k_scan() {
    __shared__ int buf[1024];
    __shared__ int carry;
    int tid = threadIdx.x;
    if (tid == 0) carry = 0;
    __syncthreads();
    for (int base = 0; base < NN; base += 1024) {
        int i = base + tid;
        int val = (i < NN) ? g_deg[i] : 0;
        buf[tid] = val;
        __syncthreads();
        for (int off = 1; off < 1024; off <<= 1) {
            int t2 = (tid >= off) ? buf[tid - off] : 0;
            __syncthreads();
            buf[tid] += t2;
            __syncthreads();
        }
        if (i < NN) g_off[i] = carry + buf[tid] - val;   // exclusive
        __syncthreads();
        if (tid == 0) carry += buf[1023];
        __syncthreads();
    }
    if (tid == 0) g_off[NN] = carry;
}

__global__ void k_fill(const int* __restrict__ ei) {
    int e = blockIdx.x * blockDim.x + threadIdx.x;
    if (e < EE) {
        int s = ei[e];
        int d = ei[EE + e];
        int pos = g_off[d] + atomicAdd(&g_cnt[d], 1);
        g_csrc[pos] = s;
        g_cw[pos]   = g_dinv[s] * g_dinv[d];
    }
}

__global__ void k_rsum() {
    int n = blockIdx.x * blockDim.x + threadIdx.x;
    if (n < NN) {
        float r = g_snorm[n];
        int e1 = g_off[n + 1];
        for (int e = g_off[n]; e < e1; e++) r += g_cw[e];
        g_rsum[n] = r;
    }
}

__global__ void k_params(const float* __restrict__ bg, const float* __restrict__ bb,
                         const float* __restrict__ bm, const float* __restrict__ bv,
                         const float* __restrict__ lw) {
    int j = threadIdx.x;
    if (j < HH) {
        float s = bg[j] * rsqrtf(bv[j] + EPS_BN);
        g_ss[j] = s;
        g_cs[j] = bb[j] - bm[j] * s;
        float acc = 0.f;
        for (int o = 0; o < HH; o++) acc += lw[o * HH + j];
        g_lwsum[j] = acc;
    }
}

// ---------------- per-step: aggregate raw x chunk (64 wide) --------------
__global__ void k_agg64(const float* __restrict__ x, int t) {
    int n = blockIdx.x * 4 + threadIdx.y;
    if (n >= NN) return;
    int c = threadIdx.x;   // 0..63
    int base = t * CH + c;
    float acc = g_snorm[n] * x[n * CIN + base];
    int e0 = g_off[n], e1 = g_off[n + 1];
#pragma unroll 4
    for (int e = e0; e < e1; e++) {
        int s = g_csrc[e];
        acc += g_cw[e] * x[s * CIN + base];
    }
    g_aggx[n * CH + c] = acc;
}

// ---------------- per-step: aggregate h2 (96 wide) -----------------------
__global__ void k_agg96() {
    int n = blockIdx.x * 4 + threadIdx.y;
    if (n >= NN) return;
    int c = threadIdx.x;   // 0..95
    float acc = g_snorm[n] * g_h2[n * HH + c];
    int e0 = g_off[n], e1 = g_off[n + 1];
#pragma unroll 4
    for (int e = e0; e < e1; e++) {
        int s = g_csrc[e];
        acc += g_cw[e] * g_h2[s * HH + c];
    }
    g_agg2[n * HH + c] = acc;
}

// ---------------- GEMM1: (agg*s1 + r*c1) @ w1t + b1t -> elu -> bns -> h2 --
// [64 nodes x 64 k] @ [64 k x 96 j], 384 threads, 4x4 register tiles.
__global__ __launch_bounds__(384) void k_gemm1(
    const float* __restrict__ w1, const float* __restrict__ b1,
    const float* __restrict__ g1, const float* __restrict__ bb1,
    const float* __restrict__ m1, const float* __restrict__ v1, int t)
{
    __shared__ float s1[CH], c1[CH];
    __shared__ float a_s[CH][68];     // [k][m], padded, 16B-aligned rows
    __shared__ float w_s[CH][HH];

    int tid = threadIdx.x;
    int m0  = blockIdx.x * 64;

    if (tid < CH) {
        float s = g1[t * CH + tid] * rsqrtf(v1[t * CH + tid] + EPS_BN);
        s1[tid] = s;
        c1[tid] = bb1[t * CH + tid] - m1[t * CH + tid] * s;
    }
    __syncthreads();

    for (int idx = tid; idx < 64 * CH; idx += 384) {
        int m = idx / CH, k = idx % CH;
        int n = m0 + m;
        float val = 0.f;
        if (n < NN) val = g_aggx[n * CH + k] * s1[k] + g_rsum[n] * c1[k];
        a_s[k][m] = val;
    }
    const float* wt = w1 + t * CH * HH;
    for (int idx = tid; idx < CH * HH; idx += 384)
        w_s[idx / HH][idx % HH] = wt[idx];
    __syncthreads();

    int mt = (tid & 15) * 4;   // 0..60
    int jt = (tid >> 4) * 4;   // 0..92
    float acc[4][4] = {};
#pragma unroll 8
    for (int k = 0; k < CH; k++) {
        float4 av = *(const float4*)&a_s[k][mt];
        float4 wv = *(const float4*)&w_s[k][jt];
        acc[0][0] += av.x * wv.x; acc[0][1] += av.x * wv.y; acc[0][2] += av.x * wv.z; acc[0][3] += av.x * wv.w;
        acc[1][0] += av.y * wv.x; acc[1][1] += av.y * wv.y; acc[1][2] += av.y * wv.z; acc[1][3] += av.y * wv.w;
        acc[2][0] += av.z * wv.x; acc[2][1] += av.z * wv.y; acc[2][2] += av.z * wv.z; acc[2][3] += av.z * wv.w;
        acc[3][0] += av.w * wv.x; acc[3][1] += av.w * wv.y; acc[3][2] += av.w * wv.z; acc[3][3] += av.w * wv.w;
    }

    const float* b1t = b1 + t * HH;
    float bj[4], ssj[4], csj[4];
#pragma unroll
    for (int j = 0; j < 4; j++) {
        bj[j]  = b1t[jt + j];
        ssj[j] = g_ss[jt + j];
        csj[j] = g_cs[jt + j];
    }
#pragma unroll
    for (int i = 0; i < 4; i++) {
        int n = m0 + mt + i;
        if (n < NN) {
            float o[4];
#pragma unroll
            for (int j = 0; j < 4; j++) {
                float z = acc[i][j] + bj[j];
                z = (z > 0.f) ? z : expm1f(z);
                o[j] = z * ssj[j] + csj[j];
            }
            *(float4*)&g_h2[n * HH + jt] = make_float4(o[0], o[1], o[2], o[3]);
        }
    }
}

// ---------------- GEMM2: agg2 @ w2 + b2 -> PLIF -> spike -> decode --------
// dynamic smem: a_s[96*68] | w_s[96*96] | lws[96] | nacc[64]
#define SMEM2_FLOATS (HH * 68 + HH * HH + HH + 64)
__global__ __launch_bounds__(384) void k_gemm2(
    const float* __restrict__ w2, const float* __restrict__ b2,
    const float* __restrict__ tau, float* __restrict__ out, int t)
{
    extern __shared__ float dsm[];
    float* a_s  = dsm;                    // [96][68]
    float* w_s  = dsm + HH * 68;          // [96][96]
    float* lws  = w_s + HH * HH;          // [96]
    float* nacc = lws + HH;               // [64]

    int tid = threadIdx.x;
    int m0  = blockIdx.x * 64;

    if (tid < HH) lws[tid] = g_lwsum[tid];
    if (tid < 64) nacc[tid] = 0.f;

    for (int idx = tid; idx < 64 * HH; idx += 384) {
        int m = idx / HH, k = idx % HH;
        int n = m0 + m;
        a_s[k * 68 + m] = (n < NN) ? g_agg2[n * HH + k] : 0.f;
    }
    for (int idx = tid; idx < HH * HH; idx += 384)
        w_s[idx] = w2[idx];
    __syncthreads();

    int mt = (tid & 15) * 4;
    int jt = (tid >> 4) * 4;
    float acc[4][4] = {};
#pragma unroll 8
    for (int k = 0; k < HH; k++) {
        float4 av = *(const float4*)&a_s[k * 68 + mt];
        float4 wv = *(const float4*)&w_s[k * HH + jt];
        acc[0][0] += av.x * wv.x; acc[0][1] += av.x * wv.y; acc[0][2] += av.x * wv.z; acc[0][3] += av.x * wv.w;
        acc[1][0] += av.y * wv.x; acc[1][1] += av.y * wv.y; acc[1][2] += av.y * wv.z; acc[1][3] += av.y * wv.w;
        acc[2][0] += av.z * wv.x; acc[2][1] += av.z * wv.y; acc[2][2] += av.z * wv.z; acc[2][3] += av.z * wv.w;
        acc[3][0] += av.w * wv.x; acc[3][1] += av.w * wv.y; acc[3][2] += av.w * wv.z; acc[3][3] += av.w * wv.w;
    }

    float tauv = *tau;
    float bj[4], lj[4];
#pragma unroll
    for (int j = 0; j < 4; j++) { bj[j] = b2[jt + j]; lj[j] = lws[jt + j]; }

#pragma unroll
    for (int i = 0; i < 4; i++) {
        int n = m0 + mt + i;
        if (n < NN) {
            float4 vv = *(float4*)&g_v[n * HH + jt];
            float vc[4] = {vv.x, vv.y, vv.z, vv.w};
            float vo[4];
            float pl = 0.f;
#pragma unroll
            for (int j = 0; j < 4; j++) {
                float dv = acc[i][j] + bj[j];
                float q  = dv - vc[j];
                float vnew = vc[j] + ((tauv == 1.0f) ? q : q / tauv);
                float u = vnew - VTH;
                bool sp = (u > 0.f);
                vo[j] = sp ? 0.f : vnew;
                if (sp) pl += lj[j];
            }
            *(float4*)&g_v[n * HH + jt] = make_float4(vo[0], vo[1], vo[2], vo[3]);
            atomicAdd(&nacc[mt + i], pl);
        }
    }
    __syncthreads();
    if (tid < 64) {
        int n = m0 + tid;
        if (n < NN) out[t * NN + n] = nacc[tid];
    }
}

// ---------------- launch --------------------------------------------------
extern "C" void kernel_launch(void* const* d_in, const int* in_sizes, int n_in,
                              void* d_out, int out_size) {
    const float* x      = (const float*)d_in[0];
    const int*   ei     = (const int*)  d_in[1];
    const float* w1     = (const float*)d_in[2];
    const float* b1     = (const float*)d_in[3];
    const float* bn1_g  = (const float*)d_in[4];
    const float* bn1_b  = (const float*)d_in[5];
    const float* bn1_m  = (const float*)d_in[6];
    const float* bn1_v  = (const float*)d_in[7];
    const float* bns_g  = (const float*)d_in[8];
    const float* bns_b  = (const float*)d_in[9];
    const float* bns_m  = (const float*)d_in[10];
    const float* bns_v  = (const float*)d_in[11];
    const float* w2     = (const float*)d_in[12];
    const float* b2     = (const float*)d_in[13];
    const float* lin_w  = (const float*)d_in[14];
    const float* tau    = (const float*)d_in[15];
    float* out = (float*)d_out;

    static bool attr_set = false;
    if (!attr_set) {
        cudaFuncSetAttribute(k_gemm2, cudaFuncAttributeMaxDynamicSharedMemorySize,
                             SMEM2_FLOATS * (int)sizeof(float));
        attr_set = true;
    }

    int nb_n = (NN + 255) / 256;
    int nb_e = (EE + 255) / 256;

    k_init<<<nb_n, 256>>>();
    k_zero_v<<<(NN * HH + 255) / 256, 256>>>();
    k_deg<<<nb_e, 256>>>(ei);
    k_dinv<<<nb_n, 256>>>();
    k_scan<<<1, 1024>>>();
    k_fill<<<nb_e, 256>>>(ei);
    k_rsum<<<nb_n, 256>>>();
    k_params<<<1, 128>>>(bns_g, bns_b, bns_m, bns_v, lin_w);

    int nb_agg  = (NN + 3) / 4;          // 12500
    int nb_gemm = (NN + 63) / 64;        // 782
    for (int t = 0; t < TT; t++) {
        k_agg64<<<nb_agg, dim3(64, 4)>>>(x, t);
        k_gemm1<<<nb_gemm, 384>>>(w1, b1, bn1_g, bn1_b, bn1_m, bn1_v, t);
        k_agg96<<<nb_agg, dim3(96, 4)>>>();
        k_gemm2<<<nb_gemm, 384, SMEM2_FLOATS * (int)sizeof(float)>>>(w2, b2, tau, out, t);
    }
}

// round 4
// speedup vs baseline: 1.3300x; 1.3300x over previous
#include <cuda_runtime.h>
#include <math.h>

#define NN    50000
#define EE    800000
#define TT    32
#define CH    64          // CHUNK = CIN/T
#define HH    96
#define CIN   2048
#define EPS_BN 1e-5f
#define VTH    0.005f

// ---------------- persistent device scratch (no allocation allowed) -------
__device__ int   g_deg[NN];
__device__ int   g_cnt[NN];
__device__ int   g_off[NN + 1];
__device__ int   g_csrc[EE];
__device__ float g_cw[EE];
__device__ float g_dinv[NN];
__device__ float g_snorm[NN];
__device__ float g_rsum[NN];
__device__ float g_h2[NN * HH];     // bns(elu(z1))
__device__ float g_v[NN * HH];      // PLIF membrane state
__device__ float g_ss[HH];          // shared-BN scale
__device__ float g_cs[HH];          // shared-BN shift
__device__ float g_lwsum[HH];       // sum(lin_w, axis=0)
__device__ float g_s1[TT * CH];     // input-BN scale, all steps
__device__ float g_c1[TT * CH];     // input-BN shift, all steps

// ---------------- preprocessing kernels ----------------------------------
__global__ void k_init() {
    int i = blockIdx.x * blockDim.x + threadIdx.x;
    if (i < NN) { g_deg[i] = 0; g_cnt[i] = 0; }
}

__global__ void k_zero_v() {
    int i = blockIdx.x * blockDim.x + threadIdx.x;
    if (i < NN * HH) g_v[i] = 0.f;
}

__global__ void k_deg(const int* __restrict__ ei) {
    int e = blockIdx.x * blockDim.x + threadIdx.x;
    if (e < EE) atomicAdd(&g_deg[ei[EE + e]], 1);
}

__global__ void k_dinv() {
    int i = blockIdx.x * blockDim.x + threadIdx.x;
    if (i < NN) {
        float d = (float)(g_deg[i] + 1);
        g_dinv[i]  = rsqrtf(d);
        g_snorm[i] = 1.0f / d;
    }
}

// single-block exclusive scan of g_deg -> g_off
__global__ void k_scan() {
    __shared__ int buf[1024];
    __shared__ int carry;
    int tid = threadIdx.x;
    if (tid == 0) carry = 0;
    __syncthreads();
    for (int base = 0; base < NN; base += 1024) {
        int i = base + tid;
        int val = (i < NN) ? g_deg[i] : 0;
        buf[tid] = val;
        __syncthreads();
        for (int off = 1; off < 1024; off <<= 1) {
            int t2 = (tid >= off) ? buf[tid - off] : 0;
            __syncthreads();
            buf[tid] += t2;
            __syncthreads();
        }
        if (i < NN) g_off[i] = carry + buf[tid] - val;   // exclusive
        __syncthreads();
        if (tid == 0) carry += buf[1023];
        __syncthreads();
    }
    if (tid == 0) g_off[NN] = carry;
}

__global__ void k_fill(const int* __restrict__ ei) {
    int e = blockIdx.x * blockDim.x + threadIdx.x;
    if (e < EE) {
        int s = ei[e];
        int d = ei[EE + e];
        int pos = g_off[d] + atomicAdd(&g_cnt[d], 1);
        g_csrc[pos] = s;
        g_cw[pos]   = g_dinv[s] * g_dinv[d];
    }
}

__global__ void k_rsum() {
    int n = blockIdx.x * blockDim.x + threadIdx.x;
    if (n < NN) {
        float r = g_snorm[n];
        int e1 = g_off[n + 1];
        for (int e = g_off[n]; e < e1; e++) r += g_cw[e];
        g_rsum[n] = r;
    }
}

// precompute shared-BN affine, lwsum, and ALL per-step input-BN affines
__global__ void k_params(const float* __restrict__ bg, const float* __restrict__ bb,
                         const float* __restrict__ bm, const float* __restrict__ bv,
                         const float* __restrict__ lw,
                         const float* __restrict__ g1, const float* __restrict__ b1,
                         const float* __restrict__ m1, const float* __restrict__ v1) {
    int i = blockIdx.x * blockDim.x + threadIdx.x;
    if (i < TT * CH) {
        float s = g1[i] * rsqrtf(v1[i] + EPS_BN);
        g_s1[i] = s;
        g_c1[i] = b1[i] - m1[i] * s;
    }
    if (i < HH) {
        float s = bg[i] * rsqrtf(bv[i] + EPS_BN);
        g_ss[i] = s;
        g_cs[i] = bb[i] - bm[i] * s;
        float acc = 0.f;
        for (int o = 0; o < HH; o++) acc += lw[o * HH + i];
        g_lwsum[i] = acc;
    }
}

// ---------------- step kernel 1: agg(x chunk)+BN fold -> GEMM1 -> elu -> bns
// 64-node tile, 384 threads. smem: a_s 64x68, w_s 64x96 (static, ~42KB).
__global__ __launch_bounds__(384) void k_step1(
    const float* __restrict__ x, const float* __restrict__ w1,
    const float* __restrict__ b1, int t)
{
    __shared__ float a_s[CH][68];     // [k][m]
    __shared__ float w_s[CH][HH];

    int tid  = threadIdx.x;
    int warp = tid >> 5;
    int lane = tid & 31;
    int m0   = blockIdx.x * 64;

    // load weight tile
    const float* wt = w1 + t * CH * HH;
    for (int idx = tid; idx < CH * HH; idx += 384)
        w_s[idx / HH][idx % HH] = wt[idx];

    // fused aggregation: each warp owns nodes m = warp, warp+12, ...
    const float* s1 = g_s1 + t * CH;
    const float* c1 = g_c1 + t * CH;
    float s1a = s1[lane], s1b = s1[lane + 32];
    float c1a = c1[lane], c1b = c1[lane + 32];
    for (int m = warp; m < 64; m += 12) {
        int n = m0 + m;
        if (n >= NN) { a_s[lane][m] = 0.f; a_s[lane + 32][m] = 0.f; continue; }
        const float* xb = x + (size_t)n * CIN + t * CH;
        float sn = g_snorm[n];
        float a0 = sn * xb[lane];
        float a1 = sn * xb[lane + 32];
        int e0 = g_off[n], e1 = g_off[n + 1];
        for (int e = e0; e < e1; e++) {
            int   s = g_csrc[e];
            float w = g_cw[e];
            const float* xs = x + (size_t)s * CIN + t * CH;
            a0 += w * xs[lane];
            a1 += w * xs[lane + 32];
        }
        float r = g_rsum[n];
        a_s[lane][m]      = a0 * s1a + r * c1a;
        a_s[lane + 32][m] = a1 * s1b + r * c1b;
    }
    __syncthreads();

    int mt = (tid & 15) * 4;   // 0..60
    int jt = (tid >> 4) * 4;   // 0..92
    float acc[4][4] = {};
#pragma unroll 8
    for (int k = 0; k < CH; k++) {
        float4 av = *(const float4*)&a_s[k][mt];
        float4 wv = *(const float4*)&w_s[k][jt];
        acc[0][0] += av.x * wv.x; acc[0][1] += av.x * wv.y; acc[0][2] += av.x * wv.z; acc[0][3] += av.x * wv.w;
        acc[1][0] += av.y * wv.x; acc[1][1] += av.y * wv.y; acc[1][2] += av.y * wv.z; acc[1][3] += av.y * wv.w;
        acc[2][0] += av.z * wv.x; acc[2][1] += av.z * wv.y; acc[2][2] += av.z * wv.z; acc[2][3] += av.z * wv.w;
        acc[3][0] += av.w * wv.x; acc[3][1] += av.w * wv.y; acc[3][2] += av.w * wv.z; acc[3][3] += av.w * wv.w;
    }

    const float* b1t = b1 + t * HH;
    float bj[4], ssj[4], csj[4];
#pragma unroll
    for (int j = 0; j < 4; j++) {
        bj[j]  = b1t[jt + j];
        ssj[j] = g_ss[jt + j];
        csj[j] = g_cs[jt + j];
    }
#pragma unroll
    for (int i = 0; i < 4; i++) {
        int n = m0 + mt + i;
        if (n < NN) {
            float o[4];
#pragma unroll
            for (int j = 0; j < 4; j++) {
                float z = acc[i][j] + bj[j];
                z = (z > 0.f) ? z : expm1f(z);
                o[j] = z * ssj[j] + csj[j];
            }
            *(float4*)&g_h2[n * HH + jt] = make_float4(o[0], o[1], o[2], o[3]);
        }
    }
}

// ---------------- step kernel 2: agg(h2) -> GEMM2 -> PLIF -> spike -> decode
// dynamic smem: a_s[96*68] | w_s[96*96] | lws[96] | nacc[64]
#define SMEM2_FLOATS (HH * 68 + HH * HH + HH + 64)
__global__ __launch_bounds__(384) void k_step2(
    const float* __restrict__ w2, const float* __restrict__ b2,
    const float* __restrict__ tau, float* __restrict__ out, int t)
{
    extern __shared__ float dsm[];
    float* a_s  = dsm;                    // [96][68]
    float* w_s  = dsm + HH * 68;          // [96][96]
    float* lws  = w_s + HH * HH;          // [96]
    float* nacc = lws + HH;               // [64]

    int tid  = threadIdx.x;
    int warp = tid >> 5;
    int lane = tid & 31;
    int m0   = blockIdx.x * 64;

    if (tid < HH) lws[tid] = g_lwsum[tid];
    if (tid < 64) nacc[tid] = 0.f;
    for (int idx = tid; idx < HH * HH; idx += 384)
        w_s[idx] = w2[idx];

    // fused aggregation of h2 (96-wide); lane covers channels lane, +32, +64
    for (int m = warp; m < 64; m += 12) {
        int n = m0 + m;
        if (n >= NN) {
            a_s[lane * 68 + m] = 0.f;
            a_s[(lane + 32) * 68 + m] = 0.f;
            a_s[(lane + 64) * 68 + m] = 0.f;
            continue;
        }
        const float* hb = g_h2 + n * HH;
        float sn = g_snorm[n];
        float a0 = sn * hb[lane];
        float a1 = sn * hb[lane + 32];
        float a2 = sn * hb[lane + 64];
        int e0 = g_off[n], e1 = g_off[n + 1];
        for (int e = e0; e < e1; e++) {
            int   s = g_csrc[e];
            float w = g_cw[e];
            const float* hs = g_h2 + s * HH;
            a0 += w * hs[lane];
            a1 += w * hs[lane + 32];
            a2 += w * hs[lane + 64];
        }
        a_s[lane * 68 + m]        = a0;
        a_s[(lane + 32) * 68 + m] = a1;
        a_s[(lane + 64) * 68 + m] = a2;
    }
    __syncthreads();

    int mt = (tid & 15) * 4;
    int jt = (tid >> 4) * 4;
    float acc[4][4] = {};
#pragma unroll 8
    for (int k = 0; k < HH; k++) {
        float4 av = *(const float4*)&a_s[k * 68 + mt];
        float4 wv = *(const float4*)&w_s[k * HH + jt];
        acc[0][0] += av.x * wv.x; acc[0][1] += av.x * wv.y; acc[0][2] += av.x * wv.z; acc[0][3] += av.x * wv.w;
        acc[1][0] += av.y * wv.x; acc[1][1] += av.y * wv.y; acc[1][2] += av.y * wv.z; acc[1][3] += av.y * wv.w;
        acc[2][0] += av.z * wv.x; acc[2][1] += av.z * wv.y; acc[2][2] += av.z * wv.z; acc[2][3] += av.z * wv.w;
        acc[3][0] += av.w * wv.x; acc[3][1] += av.w * wv.y; acc[3][2] += av.w * wv.z; acc[3][3] += av.w * wv.w;
    }

    float tauv = *tau;
    float bj[4], lj[4];
#pragma unroll
    for (int j = 0; j < 4; j++) { bj[j] = b2[jt + j]; lj[j] = lws[jt + j]; }

#pragma unroll
    for (int i = 0; i < 4; i++) {
        int n = m0 + mt + i;
        if (n < NN) {
            float4 vv = *(float4*)&g_v[n * HH + jt];
            float vc[4] = {vv.x, vv.y, vv.z, vv.w};
            float vo[4];
            float pl = 0.f;
#pragma unroll
            for (int j = 0; j < 4; j++) {
                float dv = acc[i][j] + bj[j];
                float q  = dv - vc[j];
                float vnew = vc[j] + ((tauv == 1.0f) ? q : q / tauv);
                float u = vnew - VTH;
                bool sp = (u > 0.f);
                vo[j] = sp ? 0.f : vnew;
                if (sp) pl += lj[j];
            }
            *(float4*)&g_v[n * HH + jt] = make_float4(vo[0], vo[1], vo[2], vo[3]);
            atomicAdd(&nacc[mt + i], pl);
        }
    }
    __syncthreads();
    if (tid < 64) {
        int n = m0 + tid;
        if (n < NN) out[t * NN + n] = nacc[tid];
    }
}

// ---------------- launch --------------------------------------------------
extern "C" void kernel_launch(void* const* d_in, const int* in_sizes, int n_in,
                              void* d_out, int out_size) {
    const float* x      = (const float*)d_in[0];
    const int*   ei     = (const int*)  d_in[1];
    const float* w1     = (const float*)d_in[2];
    const float* b1     = (const float*)d_in[3];
    const float* bn1_g  = (const float*)d_in[4];
    const float* bn1_b  = (const float*)d_in[5];
    const float* bn1_m  = (const float*)d_in[6];
    const float* bn1_v  = (const float*)d_in[7];
    const float* bns_g  = (const float*)d_in[8];
    const float* bns_b  = (const float*)d_in[9];
    const float* bns_m  = (const float*)d_in[10];
    const float* bns_v  = (const float*)d_in[11];
    const float* w2     = (const float*)d_in[12];
    const float* b2     = (const float*)d_in[13];
    const float* lin_w  = (const float*)d_in[14];
    const float* tau    = (const float*)d_in[15];
    float* out = (float*)d_out;

    static bool attr_set = false;
    if (!attr_set) {
        cudaFuncSetAttribute(k_step2, cudaFuncAttributeMaxDynamicSharedMemorySize,
                             SMEM2_FLOATS * (int)sizeof(float));
        attr_set = true;
    }

    int nb_n = (NN + 255) / 256;
    int nb_e = (EE + 255) / 256;

    k_init<<<nb_n, 256>>>();
    k_zero_v<<<(NN * HH + 255) / 256, 256>>>();
    k_deg<<<nb_e, 256>>>(ei);
    k_dinv<<<nb_n, 256>>>();
    k_scan<<<1, 1024>>>();
    k_fill<<<nb_e, 256>>>(ei);
    k_rsum<<<nb_n, 256>>>();
    k_params<<<(TT * CH + 255) / 256, 256>>>(bns_g, bns_b, bns_m, bns_v, lin_w,
                                             bn1_g, bn1_b, bn1_m, bn1_v);

    int nb_gemm = (NN + 63) / 64;        // 782
    for (int t = 0; t < TT; t++) {
        k_step1<<<nb_gemm, 384>>>(x, w1, b1, t);
        k_step2<<<nb_gemm, 384, SMEM2_FLOATS * (int)sizeof(float)>>>(w2, b2, tau, out, t);
    }
}